// round 13
// baseline (speedup 1.0000x reference)
#include <cuda_runtime.h>
#include <cuda_bf16.h>
#include <cuda_fp16.h>
#include <math.h>
#include <stdint.h>

#define Bq   4
#define Nq   200000
#define Eq   128
#define IDXq 2048
#define TOT  (Bq * Nq)        // 800000 tokens
#define SEGS (Bq * IDXq)      // 8192 segments
#define OUTF (SEGS * Eq)      // 1048576 floats in `out` region
#define TM   128              // tokens per tile
#define TILES (TOT / TM)      // 6250 tiles
#define ROWB 272              // padded bf16 smem row stride (128 bf16 + 8 pad)
#define RAWS 528              // padded fp32 raw row stride bytes (132 floats)

// ---------------- device scratch (no cudaMalloc allowed) -------------------
__device__ float g_e[TOT];
__device__ float g_segsum[SEGS];
__device__ int   g_cnt[SEGS];     // unmasked token count per segment
__device__ int   g_off[SEGS];     // segment start offsets (exclusive scan)
__device__ int   g_cur[SEGS];     // place cursors -> end offsets after place
__device__ int   g_ord[TOT];      // unmasked token ids sorted by segment
__device__ float g_w[TOT];        // normalized weight per sorted position
__device__ __half g_xq[(size_t)TOT * Eq];  // fp16 copy of unmasked x rows (205MB)
__device__ __nv_bfloat16 g_Whi[Eq * Eq];
__device__ __nv_bfloat16 g_Wlo[Eq * Eq];

// ---------------- helpers ---------------------------------------------------
__device__ __forceinline__ uint32_t smem_u32(const void* p) {
    uint32_t a;
    asm("{ .reg .u64 t; cvta.to.shared.u64 t, %1; cvt.u32.u64 %0, t; }" : "=r"(a) : "l"(p));
    return a;
}
__device__ __forceinline__ uint32_t pack_bf16x2(float a, float b) {  // lo=a, hi=b
    uint32_t r;
    asm("cvt.rn.bf16x2.f32 %0, %1, %2;" : "=r"(r) : "f"(b), "f"(a));
    return r;
}
__device__ __forceinline__ uint32_t pack_f16x2(float a, float b) {   // lo=a, hi=b
    uint32_t r;
    asm("cvt.rn.f16x2.f32 %0, %1, %2;" : "=r"(r) : "f"(b), "f"(a));
    return r;
}
__device__ __forceinline__ void cp_async16(uint32_t saddr, const void* gaddr) {
    asm volatile("cp.async.cg.shared.global [%0], [%1], 16;" :: "r"(saddr), "l"(gaddr));
}
__device__ __forceinline__ void ldsm_x4(uint32_t addr, uint32_t& r0, uint32_t& r1,
                                        uint32_t& r2, uint32_t& r3) {
    asm volatile("ldmatrix.sync.aligned.m8n8.x4.shared.b16 {%0,%1,%2,%3}, [%4];"
                 : "=r"(r0), "=r"(r1), "=r"(r2), "=r"(r3) : "r"(addr));
}
__device__ __forceinline__ void mma_bf16(float* d, uint32_t a0, uint32_t a1, uint32_t a2,
                                         uint32_t a3, uint32_t b0, uint32_t b1) {
    asm volatile(
        "mma.sync.aligned.m16n8k16.row.col.f32.bf16.bf16.f32 "
        "{%0,%1,%2,%3}, {%4,%5,%6,%7}, {%8,%9}, {%0,%1,%2,%3};"
        : "+f"(d[0]), "+f"(d[1]), "+f"(d[2]), "+f"(d[3])
        : "r"(a0), "r"(a1), "r"(a2), "r"(a3), "r"(b0), "r"(b1));
}
// tanh(x) = 1 - 2/(exp(2x)+1), via ex2.approx + rcp.approx (~2^-21 max rel err)
__device__ __forceinline__ float fast_tanh(float x) {
    float e, r;
    asm("ex2.approx.f32 %0, %1;" : "=f"(e) : "f"(x * 2.8853900817779268f));
    asm("rcp.approx.f32 %0, %1;" : "=f"(r) : "f"(e + 1.0f));
    return fmaf(-2.0f, r, 1.0f);
}
__device__ __forceinline__ void bar64(int id) {
    asm volatile("bar.sync %0, 64;" :: "r"(id) : "memory");
}

// ---------------------------------------------------------------------------
__global__ void wprep_kernel(const float* __restrict__ W) {
    int i = blockIdx.x * blockDim.x + threadIdx.x; // 16384 exact
    float w = W[i];
    __nv_bfloat16 hi = __float2bfloat16_rn(w);
    g_Whi[i] = hi;
    g_Wlo[i] = __float2bfloat16_rn(w - __bfloat162float(hi));
}

// zero per-segment accumulators (idempotent across graph replays)
__global__ void zinit_kernel() {
    int i = blockIdx.x * blockDim.x + threadIdx.x;   // grid covers SEGS
    g_segsum[i] = 0.0f;
    g_cnt[i] = 0;
}

// ---------------------------------------------------------------------------
// Score pass: persistent HMMA bf16x3-split GEMM, cp.async pipelined.
// Decoupled into four independent 64-thread groups (2 warps each): group g
// owns tile rows 32g..32g+31 end-to-end (convert, MMA A-fragments, finalize),
// synced only by pair-local named barriers -> tensor/FMA phases of different
// groups overlap on the SMSPs. Emits e = mask ? exp(score) : 0, segsum, cnt,
// and an fp16 copy of unmasked x rows for the gather pass.
// ---------------------------------------------------------------------------
#define SM_B   0
#define SM_C   512
#define SM_P   1024                     // partial[128][2] floats
#define SM_WH  2048
#define SM_WL  (SM_WH + 128 * ROWB)
#define SM_XH  (SM_WL + 128 * ROWB)
#define SM_XL  (SM_XH + 128 * ROWB)
#define SM_RAW (SM_XL + 128 * ROWB)     // fp32 raw tile, stride 528B
#define SM_TOTAL (SM_RAW + 128 * RAWS)  // 208896

__global__ void __launch_bounds__(256, 1) score_kernel(
    const float* __restrict__ x, const float* __restrict__ bias,
    const float* __restrict__ ctx, const int* __restrict__ mask,
    const int* __restrict__ index)
{
    extern __shared__ char smem[];
    const uint32_t sb = smem_u32(smem);
    const int tid  = threadIdx.x;
    const int wid  = tid >> 5;
    const int lane = tid & 31;
    const int group = wid >> 1;
    const int barid = 1 + group;

    float* bS = reinterpret_cast<float*>(smem + SM_B);
    float* cS = reinterpret_cast<float*>(smem + SM_C);
    float* pS = reinterpret_cast<float*>(smem + SM_P);
    if (tid < 128) { bS[tid] = bias[tid]; cS[tid] = ctx[tid]; }

    // stage W hi/lo (row f, stride 272B). 256 thr, 128 rows.
    {
        const int r = tid >> 1;
        const int c0 = (tid & 1) * 64;
#pragma unroll
        for (int i = 0; i < 8; i++) {
            const int c = c0 + i * 8;
            *reinterpret_cast<uint4*>(smem + SM_WH + r * ROWB + c * 2) =
                *reinterpret_cast<const uint4*>(&g_Whi[r * Eq + c]);
            *reinterpret_cast<uint4*>(smem + SM_WL + r * ROWB + c * 2) =
                *reinterpret_cast<const uint4*>(&g_Wlo[r * Eq + c]);
        }
    }

    const int xr   = tid >> 1;          // row owned by this thread (in group rows)
    const int half = (tid & 1) * 64;
    const uint32_t rawBase = sb + SM_RAW + (uint32_t)xr * RAWS + (uint32_t)half * 4;

    const int rowG = group * 32;
    const int colG = (wid & 1) * 64;

    const uint32_t aColB = (lane >> 4) * 16;
    const uint32_t aAddr0H = sb + SM_XH + (uint32_t)(rowG + (lane & 15)) * ROWB + aColB;
    const uint32_t aAddr1H = aAddr0H + 16 * ROWB;
    const uint32_t dXL = (uint32_t)(SM_XL - SM_XH);
    const int rowB = (lane & 7) + ((lane & 16) >> 1);
    const uint32_t colB = (lane & 8) ? 16u : 0u;
    const uint32_t bBaseH = sb + SM_WH + (uint32_t)(colG + rowB) * ROWB + colB;
    const uint32_t dWL = (uint32_t)(SM_WL - SM_WH);

    __syncthreads();   // W/bias/ctx staged (the ONLY block-wide barrier)

    // convert helper macro body reused inline: raw row -> XH/XL rows (+ fp16 copy)
    // ---- prologue: cp.async tile0 -> raw, convert ----
    int tile = blockIdx.x;
    {
        const float* xrow = x + (size_t)(tile * TM + xr) * Eq + half;
#pragma unroll
        for (int i = 0; i < 16; i++) cp_async16(rawBase + i * 16, xrow + i * 4);
        asm volatile("cp.async.commit_group;" ::: "memory");
        asm volatile("cp.async.wait_group 0;" ::: "memory");
        const int tok = tile * TM + xr;
        const int m = mask[tok];
        __half* xqrow = g_xq + (size_t)tok * Eq + half;
#pragma unroll
        for (int i = 0; i < 8; i++) {
            float4 f0 = *reinterpret_cast<const float4*>(smem + (rawBase - sb) + i * 32);
            float4 f1 = *reinterpret_cast<const float4*>(smem + (rawBase - sb) + i * 32 + 16);
            float fv[8] = {f0.x, f0.y, f0.z, f0.w, f1.x, f1.y, f1.z, f1.w};
            float hv[8], lv[8];
#pragma unroll
            for (int j = 0; j < 8; j++) {
                hv[j] = __bfloat162float(__float2bfloat16_rn(fv[j]));
                lv[j] = fv[j] - hv[j];
            }
            uint4 uh, ul;
            uh.x = pack_bf16x2(hv[0], hv[1]); uh.y = pack_bf16x2(hv[2], hv[3]);
            uh.z = pack_bf16x2(hv[4], hv[5]); uh.w = pack_bf16x2(hv[6], hv[7]);
            ul.x = pack_bf16x2(lv[0], lv[1]); ul.y = pack_bf16x2(lv[2], lv[3]);
            ul.z = pack_bf16x2(lv[4], lv[5]); ul.w = pack_bf16x2(lv[6], lv[7]);
            const int c = half + i * 8;
            *reinterpret_cast<uint4*>(smem + SM_XH + xr * ROWB + c * 2) = uh;
            *reinterpret_cast<uint4*>(smem + SM_XL + xr * ROWB + c * 2) = ul;
            if (m) {
                uint4 q;
                q.x = pack_f16x2(fv[0], fv[1]); q.y = pack_f16x2(fv[2], fv[3]);
                q.z = pack_f16x2(fv[4], fv[5]); q.w = pack_f16x2(fv[6], fv[7]);
                *reinterpret_cast<uint4*>(xqrow + i * 8) = q;
            }
        }
    }
    bar64(barid);

    while (tile < TILES) {
        const int tbase = tile * TM;
        const int next  = tile + gridDim.x;

        // ---- issue cp.async for next tile ----
        if (next < TILES) {
            const float* xrow = x + (size_t)(next * TM + xr) * Eq + half;
#pragma unroll
            for (int i = 0; i < 16; i++) cp_async16(rawBase + i * 16, xrow + i * 4);
            asm volatile("cp.async.commit_group;" ::: "memory");
        }

        // ---- MMA mainloop: d = xh*Wh + xh*Wl + xl*Wh ----
        float d[2][8][4];
#pragma unroll
        for (int mb = 0; mb < 2; mb++)
#pragma unroll
            for (int nb = 0; nb < 8; nb++)
#pragma unroll
                for (int j = 0; j < 4; j++) d[mb][nb][j] = 0.0f;

#pragma unroll
        for (int k = 0; k < 8; k++) {
            const uint32_t ko = (uint32_t)k * 32;
            uint32_t ah[2][4], al[2][4];
            ldsm_x4(aAddr0H + ko,       ah[0][0], ah[0][1], ah[0][2], ah[0][3]);
            ldsm_x4(aAddr0H + dXL + ko, al[0][0], al[0][1], al[0][2], al[0][3]);
            ldsm_x4(aAddr1H + ko,       ah[1][0], ah[1][1], ah[1][2], ah[1][3]);
            ldsm_x4(aAddr1H + dXL + ko, al[1][0], al[1][1], al[1][2], al[1][3]);
#pragma unroll
            for (int nb = 0; nb < 4; nb++) {
                uint32_t bh0, bh1, bh2, bh3, bl0, bl1, bl2, bl3;
                const uint32_t boff = (uint32_t)nb * (16 * ROWB) + ko;
                ldsm_x4(bBaseH + boff,       bh0, bh1, bh2, bh3);
                ldsm_x4(bBaseH + dWL + boff, bl0, bl1, bl2, bl3);
#pragma unroll
                for (int mb = 0; mb < 2; mb++) {
                    mma_bf16(d[mb][nb * 2],     ah[mb][0], ah[mb][1], ah[mb][2], ah[mb][3], bh0, bh1);
                    mma_bf16(d[mb][nb * 2],     ah[mb][0], ah[mb][1], ah[mb][2], ah[mb][3], bl0, bl1);
                    mma_bf16(d[mb][nb * 2],     al[mb][0], al[mb][1], al[mb][2], al[mb][3], bh0, bh1);
                    mma_bf16(d[mb][nb * 2 + 1], ah[mb][0], ah[mb][1], ah[mb][2], ah[mb][3], bh2, bh3);
                    mma_bf16(d[mb][nb * 2 + 1], ah[mb][0], ah[mb][1], ah[mb][2], ah[mb][3], bl2, bl3);
                    mma_bf16(d[mb][nb * 2 + 1], al[mb][0], al[mb][1], al[mb][2], al[mb][3], bh2, bh3);
                }
            }
        }

        // ---- epilogue: per-warp partial of ctx . tanh(z + b) over 64 cols ----
#pragma unroll
        for (int mb = 0; mb < 2; mb++) {
            float p0 = 0.0f, p1 = 0.0f;
#pragma unroll
            for (int nb = 0; nb < 8; nb++) {
                const int n0 = colG + nb * 8 + (lane & 3) * 2;
                const float2 bb = *reinterpret_cast<const float2*>(&bS[n0]);
                const float2 cc = *reinterpret_cast<const float2*>(&cS[n0]);
                p0 = fmaf(fast_tanh(d[mb][nb][0] + bb.x), cc.x, p0);
                p0 = fmaf(fast_tanh(d[mb][nb][1] + bb.y), cc.y, p0);
                p1 = fmaf(fast_tanh(d[mb][nb][2] + bb.x), cc.x, p1);
                p1 = fmaf(fast_tanh(d[mb][nb][3] + bb.y), cc.y, p1);
            }
            p0 += __shfl_xor_sync(0xffffffffu, p0, 1);
            p0 += __shfl_xor_sync(0xffffffffu, p0, 2);
            p1 += __shfl_xor_sync(0xffffffffu, p1, 1);
            p1 += __shfl_xor_sync(0xffffffffu, p1, 2);
            if ((lane & 3) == 0) {
                const int r = rowG + mb * 16 + (lane >> 2);
                pS[r * 2 + (wid & 1)]       = p0;
                pS[(r + 8) * 2 + (wid & 1)] = p1;
            }
        }
        bar64(barid);   // group's partials visible; group's ldsm of this tile done

        // ---- finalize own rows (even thread of each pair) ----
        if ((tid & 1) == 0) {
            const int tok = tbase + xr;
            const float s = (pS[xr * 2] + pS[xr * 2 + 1]) * 0.08838834764831845f;
            const int m = mask[tok];
            const float e = (m == 0) ? 0.0f : __expf(s);
            g_e[tok] = e;
            if (m != 0) {
                const int seg = (tok / Nq) * IDXq + index[tok];
                atomicAdd(&g_segsum[seg], e);
                atomicAdd(&g_cnt[seg], 1);
            }
        }

        // ---- convert raw -> hi/lo (+ fp16 copy) for next tile ----
        asm volatile("cp.async.wait_group 0;" ::: "memory");
        if (next < TILES) {
            const int tokN = next * TM + xr;
            const int mN = mask[tokN];
            __half* xqrow = g_xq + (size_t)tokN * Eq + half;
#pragma unroll
            for (int i = 0; i < 8; i++) {
                float4 f0 = *reinterpret_cast<const float4*>(smem + (rawBase - sb) + i * 32);
                float4 f1 = *reinterpret_cast<const float4*>(smem + (rawBase - sb) + i * 32 + 16);
                float fv[8] = {f0.x, f0.y, f0.z, f0.w, f1.x, f1.y, f1.z, f1.w};
                float hv[8], lv[8];
#pragma unroll
                for (int j = 0; j < 8; j++) {
                    hv[j] = __bfloat162float(__float2bfloat16_rn(fv[j]));
                    lv[j] = fv[j] - hv[j];
                }
                uint4 uh, ul;
                uh.x = pack_bf16x2(hv[0], hv[1]); uh.y = pack_bf16x2(hv[2], hv[3]);
                uh.z = pack_bf16x2(hv[4], hv[5]); uh.w = pack_bf16x2(hv[6], hv[7]);
                ul.x = pack_bf16x2(lv[0], lv[1]); ul.y = pack_bf16x2(lv[2], lv[3]);
                ul.z = pack_bf16x2(lv[4], lv[5]); ul.w = pack_bf16x2(lv[6], lv[7]);
                const int c = half + i * 8;
                *reinterpret_cast<uint4*>(smem + SM_XH + xr * ROWB + c * 2) = uh;
                *reinterpret_cast<uint4*>(smem + SM_XL + xr * ROWB + c * 2) = ul;
                if (mN) {
                    uint4 q;
                    q.x = pack_f16x2(fv[0], fv[1]); q.y = pack_f16x2(fv[2], fv[3]);
                    q.z = pack_f16x2(fv[4], fv[5]); q.w = pack_f16x2(fv[6], fv[7]);
                    *reinterpret_cast<uint4*>(xqrow + i * 8) = q;
                }
            }
        }
        bar64(barid);   // group's new XH/XL ready before next MMA
        tile = next;
    }
}

// ---------------------------------------------------------------------------
// Scan: exclusive prefix sum of g_cnt -> g_off/g_cur. Shfl-based, 1 block.
// ---------------------------------------------------------------------------
__global__ void __launch_bounds__(1024) scan_kernel() {
    __shared__ int wsum[32];
    const int tid  = threadIdx.x;
    const int lane = tid & 31;
    const int warp = tid >> 5;

    int4 c0 = reinterpret_cast<const int4*>(g_cnt)[tid * 2];
    int4 c1 = reinterpret_cast<const int4*>(g_cnt)[tid * 2 + 1];
    int v[8] = {c0.x, c0.y, c0.z, c0.w, c1.x, c1.y, c1.z, c1.w};
    int pre[8];
    int s = 0;
#pragma unroll
    for (int j = 0; j < 8; j++) { pre[j] = s; s += v[j]; }

    int inc = s;
#pragma unroll
    for (int o = 1; o < 32; o <<= 1) {
        int t = __shfl_up_sync(0xffffffffu, inc, o);
        if (lane >= o) inc += t;
    }
    if (lane == 31) wsum[warp] = inc;
    __syncthreads();
    if (warp == 0) {
        int w = wsum[lane];
#pragma unroll
        for (int o = 1; o < 32; o <<= 1) {
            int t = __shfl_up_sync(0xffffffffu, w, o);
            if (lane >= o) w += t;
        }
        wsum[lane] = w;
    }
    __syncthreads();
    const int base = (warp > 0 ? wsum[warp - 1] : 0) + inc - s;
#pragma unroll
    for (int j = 0; j < 8; j++) {
        const int o = base + pre[j];
        g_off[tid * 8 + j] = o;
        g_cur[tid * 8 + j] = o;
    }
}

// ---------------------------------------------------------------------------
// Place: counting-sort UNMASKED tokens; precompute normalized weights;
// write attn for ALL tokens (0 when masked).
// ---------------------------------------------------------------------------
__global__ void place_kernel(const int* __restrict__ index, const int* __restrict__ mask,
                             float* __restrict__ attn) {
    const int t = blockIdx.x * blockDim.x + threadIdx.x;  // grid exact: TOT
    const int m = mask[t];
    float w = 0.0f;
    if (m != 0) {
        const int seg = (t / Nq) * IDXq + index[t];
        w = g_e[t] / g_segsum[seg];     // segsum > 0: this token contributes
        const int pos = atomicAdd(&g_cur[seg], 1);
        g_ord[pos] = t;
        g_w[pos] = w;
    }
    attn[t] = w;
}

// ---------------------------------------------------------------------------
// Gather: one warp per segment, fp16 rows, streaming ord/w.
// ---------------------------------------------------------------------------
__global__ void __launch_bounds__(256) gather_kernel(float* __restrict__ out)
{
    const int seg  = (blockIdx.x * blockDim.x + threadIdx.x) >> 5; // grid exact: SEGS warps
    const int lane = threadIdx.x & 31;
    const int start = g_off[seg];
    const int end   = g_cur[seg];

    float4 acc = make_float4(0.f, 0.f, 0.f, 0.f);
    int i = start;
    for (; i + 8 <= end; i += 8) {
        int tt[8]; float ww[8]; uint2 vv[8];
#pragma unroll
        for (int j = 0; j < 8; j++) { tt[j] = g_ord[i + j]; ww[j] = g_w[i + j]; }
#pragma unroll
        for (int j = 0; j < 8; j++)
            vv[j] = *reinterpret_cast<const uint2*>(g_xq + (size_t)tt[j] * Eq + lane * 4);
#pragma unroll
        for (int j = 0; j < 8; j++) {
            const float2 f0 = __half22float2(*reinterpret_cast<__half2*>(&vv[j].x));
            const float2 f1 = __half22float2(*reinterpret_cast<__half2*>(&vv[j].y));
            acc.x = fmaf(ww[j], f0.x, acc.x);
            acc.y = fmaf(ww[j], f0.y, acc.y);
            acc.z = fmaf(ww[j], f1.x, acc.z);
            acc.w = fmaf(ww[j], f1.y, acc.w);
        }
    }
    for (; i < end; i++) {
        const int t = g_ord[i];
        const float w = g_w[i];
        uint2 v = *reinterpret_cast<const uint2*>(g_xq + (size_t)t * Eq + lane * 4);
        const float2 f0 = __half22float2(*reinterpret_cast<__half2*>(&v.x));
        const float2 f1 = __half22float2(*reinterpret_cast<__half2*>(&v.y));
        acc.x = fmaf(w, f0.x, acc.x);
        acc.y = fmaf(w, f0.y, acc.y);
        acc.z = fmaf(w, f1.x, acc.z);
        acc.w = fmaf(w, f1.y, acc.w);
    }
    reinterpret_cast<float4*>(out + (size_t)seg * Eq)[lane] = acc;
}

// ---------------------------------------------------------------------------
extern "C" void kernel_launch(void* const* d_in, const int* in_sizes, int n_in,
                              void* d_out, int out_size)
{
    const float* x     = (const float*)d_in[0];
    const float* W     = (const float*)d_in[1];
    const float* bias  = (const float*)d_in[2];
    const float* ctx   = (const float*)d_in[3];
    const int*   mask  = (const int*)d_in[4];
    const int*   index = (const int*)d_in[5];

    float* out  = (float*)d_out;        // [B, IDX, E]
    float* attn = out + OUTF;           // [B, N]

    cudaFuncSetAttribute(score_kernel, cudaFuncAttributeMaxDynamicSharedMemorySize, SM_TOTAL);

    wprep_kernel<<<Eq * Eq / 256, 256>>>(W);
    zinit_kernel<<<SEGS / 256, 256>>>();
    score_kernel<<<152, 256, SM_TOTAL>>>(x, bias, ctx, mask, index);
    scan_kernel<<<1, 1024>>>();
    place_kernel<<<TOT / 256, 256>>>(index, mask, attn);
    gather_kernel<<<SEGS / 8, 256>>>(out);
}

// round 14
// speedup vs baseline: 1.0962x; 1.0962x over previous
#include <cuda_runtime.h>
#include <cuda_bf16.h>
#include <cuda_fp16.h>
#include <math.h>
#include <stdint.h>

#define Bq   4
#define Nq   200000
#define Eq   128
#define IDXq 2048
#define TOT  (Bq * Nq)        // 800000 tokens
#define SEGS (Bq * IDXq)      // 8192 segments
#define OUTF (SEGS * Eq)      // 1048576 floats in `out` region
#define TM   128              // tokens per tile
#define TILES (TOT / TM)      // 6250 tiles
#define ROWB 272              // padded f16 smem row stride (128 f16 + 8 pad)
#define RAWS 528              // padded fp32 raw row stride bytes (132 floats)

// ---------------- device scratch (no cudaMalloc allowed) -------------------
__device__ float g_e[TOT];
__device__ float g_segsum[SEGS];
__device__ int   g_cnt[SEGS];     // unmasked token count per segment
__device__ int   g_off[SEGS];     // segment start offsets (exclusive scan)
__device__ int   g_cur[SEGS];     // place cursors -> end offsets after place
__device__ int   g_ord[TOT];      // unmasked token ids sorted by segment
__device__ float g_w[TOT];        // normalized weight per sorted position
__device__ __half g_xq[(size_t)TOT * Eq];  // fp16 copy of unmasked x rows
__device__ __half g_Whi[Eq * Eq];
__device__ __half g_Wlo[Eq * Eq];

// ---------------- helpers ---------------------------------------------------
__device__ __forceinline__ uint32_t smem_u32(const void* p) {
    uint32_t a;
    asm("{ .reg .u64 t; cvta.to.shared.u64 t, %1; cvt.u32.u64 %0, t; }" : "=r"(a) : "l"(p));
    return a;
}
__device__ __forceinline__ uint32_t pack_f16x2(float a, float b) {   // lo=a, hi=b
    uint32_t r;
    asm("cvt.rn.f16x2.f32 %0, %1, %2;" : "=r"(r) : "f"(b), "f"(a));
    return r;
}
__device__ __forceinline__ void cp_async16(uint32_t saddr, const void* gaddr) {
    asm volatile("cp.async.cg.shared.global [%0], [%1], 16;" :: "r"(saddr), "l"(gaddr));
}
__device__ __forceinline__ void ldsm_x4(uint32_t addr, uint32_t& r0, uint32_t& r1,
                                        uint32_t& r2, uint32_t& r3) {
    asm volatile("ldmatrix.sync.aligned.m8n8.x4.shared.b16 {%0,%1,%2,%3}, [%4];"
                 : "=r"(r0), "=r"(r1), "=r"(r2), "=r"(r3) : "r"(addr));
}
// fp16 inputs, fp32 accumulator (main term)
__device__ __forceinline__ void mma_f32acc(float* d, uint32_t a0, uint32_t a1, uint32_t a2,
                                           uint32_t a3, uint32_t b0, uint32_t b1) {
    asm volatile(
        "mma.sync.aligned.m16n8k16.row.col.f32.f16.f16.f32 "
        "{%0,%1,%2,%3}, {%4,%5,%6,%7}, {%8,%9}, {%0,%1,%2,%3};"
        : "+f"(d[0]), "+f"(d[1]), "+f"(d[2]), "+f"(d[3])
        : "r"(a0), "r"(a1), "r"(a2), "r"(a3), "r"(b0), "r"(b1));
}
// fp16 inputs, fp16 accumulator (residual terms; 2 f16x2 regs)
__device__ __forceinline__ void mma_f16acc(uint32_t* d, uint32_t a0, uint32_t a1, uint32_t a2,
                                           uint32_t a3, uint32_t b0, uint32_t b1) {
    asm volatile(
        "mma.sync.aligned.m16n8k16.row.col.f16.f16.f16.f16 "
        "{%0,%1}, {%2,%3,%4,%5}, {%6,%7}, {%0,%1};"
        : "+r"(d[0]), "+r"(d[1])
        : "r"(a0), "r"(a1), "r"(a2), "r"(a3), "r"(b0), "r"(b1));
}
// tanh(x) = 1 - 2/(exp(2x)+1), via ex2.approx + rcp.approx (~2^-21 max rel err)
__device__ __forceinline__ float fast_tanh(float x) {
    float e, r;
    asm("ex2.approx.f32 %0, %1;" : "=f"(e) : "f"(x * 2.8853900817779268f));
    asm("rcp.approx.f32 %0, %1;" : "=f"(r) : "f"(e + 1.0f));
    return fmaf(-2.0f, r, 1.0f);
}
__device__ __forceinline__ void bar64(int id) {
    asm volatile("bar.sync %0, 64;" :: "r"(id) : "memory");
}

// ---------------------------------------------------------------------------
__global__ void wprep_kernel(const float* __restrict__ W) {
    int i = blockIdx.x * blockDim.x + threadIdx.x; // 16384 exact
    float w = W[i];
    __half hi = __float2half_rn(w);
    g_Whi[i] = hi;
    g_Wlo[i] = __float2half_rn(w - __half2float(hi));
}

// zero per-segment accumulators (idempotent across graph replays)
__global__ void zinit_kernel() {
    int i = blockIdx.x * blockDim.x + threadIdx.x;   // grid covers SEGS
    g_segsum[i] = 0.0f;
    g_cnt[i] = 0;
}

// ---------------------------------------------------------------------------
// Score pass: persistent HMMA fp16x3-split GEMM, cp.async pipelined.
// Main term xh*Wh in fp32-acc MMA; residual xh*Wl + xl*Wh chained in ONE
// fp16-acc MMA (rt ~half of fp32-acc on sm_103 per calibration hypothesis).
// Four independent 64-thread groups (pair-local barriers). The fp16 xh tile
// doubles as the gather copy (g_xq).
// ---------------------------------------------------------------------------
#define SM_B   0
#define SM_C   512
#define SM_P   1024                     // partial[128][2] floats
#define SM_WH  2048
#define SM_WL  (SM_WH + 128 * ROWB)
#define SM_XH  (SM_WL + 128 * ROWB)
#define SM_XL  (SM_XH + 128 * ROWB)
#define SM_RAW (SM_XL + 128 * ROWB)     // fp32 raw tile, stride 528B
#define SM_TOTAL (SM_RAW + 128 * RAWS)  // 208896

__global__ void __launch_bounds__(256, 1) score_kernel(
    const float* __restrict__ x, const float* __restrict__ bias,
    const float* __restrict__ ctx, const int* __restrict__ mask,
    const int* __restrict__ index)
{
    extern __shared__ char smem[];
    const uint32_t sb = smem_u32(smem);
    const int tid  = threadIdx.x;
    const int wid  = tid >> 5;
    const int lane = tid & 31;
    const int group = wid >> 1;
    const int barid = 1 + group;

    float* bS = reinterpret_cast<float*>(smem + SM_B);
    float* cS = reinterpret_cast<float*>(smem + SM_C);
    float* pS = reinterpret_cast<float*>(smem + SM_P);
    if (tid < 128) { bS[tid] = bias[tid]; cS[tid] = ctx[tid]; }

    // stage W hi/lo (row f, stride 272B). 256 thr, 128 rows.
    {
        const int r = tid >> 1;
        const int c0 = (tid & 1) * 64;
#pragma unroll
        for (int i = 0; i < 8; i++) {
            const int c = c0 + i * 8;
            *reinterpret_cast<uint4*>(smem + SM_WH + r * ROWB + c * 2) =
                *reinterpret_cast<const uint4*>(&g_Whi[r * Eq + c]);
            *reinterpret_cast<uint4*>(smem + SM_WL + r * ROWB + c * 2) =
                *reinterpret_cast<const uint4*>(&g_Wlo[r * Eq + c]);
        }
    }

    const int xr   = tid >> 1;          // tile row owned by this thread
    const int half = (tid & 1) * 64;
    const uint32_t rawBase = sb + SM_RAW + (uint32_t)xr * RAWS + (uint32_t)half * 4;

    const int rowG = group * 32;
    const int colG = (wid & 1) * 64;

    const uint32_t aColB = (lane >> 4) * 16;
    const uint32_t aAddr0H = sb + SM_XH + (uint32_t)(rowG + (lane & 15)) * ROWB + aColB;
    const uint32_t aAddr1H = aAddr0H + 16 * ROWB;
    const uint32_t dXL = (uint32_t)(SM_XL - SM_XH);
    const int rowB = (lane & 7) + ((lane & 16) >> 1);
    const uint32_t colB = (lane & 8) ? 16u : 0u;
    const uint32_t bBaseH = sb + SM_WH + (uint32_t)(colG + rowB) * ROWB + colB;
    const uint32_t dWL = (uint32_t)(SM_WL - SM_WH);

    __syncthreads();   // W/bias/ctx staged (the ONLY block-wide barrier)

    // ---- prologue: cp.async tile0 -> raw, convert ----
    int tile = blockIdx.x;
    {
        const float* xrow = x + (size_t)(tile * TM + xr) * Eq + half;
#pragma unroll
        for (int i = 0; i < 16; i++) cp_async16(rawBase + i * 16, xrow + i * 4);
        asm volatile("cp.async.commit_group;" ::: "memory");
        asm volatile("cp.async.wait_group 0;" ::: "memory");
        const int tok = tile * TM + xr;
        const int m = mask[tok];
        __half* xqrow = g_xq + (size_t)tok * Eq + half;
#pragma unroll
        for (int i = 0; i < 8; i++) {
            float4 f0 = *reinterpret_cast<const float4*>(smem + (rawBase - sb) + i * 32);
            float4 f1 = *reinterpret_cast<const float4*>(smem + (rawBase - sb) + i * 32 + 16);
            float fv[8] = {f0.x, f0.y, f0.z, f0.w, f1.x, f1.y, f1.z, f1.w};
            float hv[8], lv[8];
#pragma unroll
            for (int j = 0; j < 8; j++) {
                hv[j] = __half2float(__float2half_rn(fv[j]));
                lv[j] = fv[j] - hv[j];
            }
            uint4 uh, ul;
            uh.x = pack_f16x2(hv[0], hv[1]); uh.y = pack_f16x2(hv[2], hv[3]);
            uh.z = pack_f16x2(hv[4], hv[5]); uh.w = pack_f16x2(hv[6], hv[7]);
            ul.x = pack_f16x2(lv[0], lv[1]); ul.y = pack_f16x2(lv[2], lv[3]);
            ul.z = pack_f16x2(lv[4], lv[5]); ul.w = pack_f16x2(lv[6], lv[7]);
            const int c = half + i * 8;
            *reinterpret_cast<uint4*>(smem + SM_XH + xr * ROWB + c * 2) = uh;
            *reinterpret_cast<uint4*>(smem + SM_XL + xr * ROWB + c * 2) = ul;
            if (m) *reinterpret_cast<uint4*>(xqrow + i * 8) = uh;  // fp16 copy == xh
        }
    }
    bar64(barid);

    while (tile < TILES) {
        const int tbase = tile * TM;
        const int next  = tile + gridDim.x;

        // ---- issue cp.async for next tile ----
        if (next < TILES) {
            const float* xrow = x + (size_t)(next * TM + xr) * Eq + half;
#pragma unroll
            for (int i = 0; i < 16; i++) cp_async16(rawBase + i * 16, xrow + i * 4);
            asm volatile("cp.async.commit_group;" ::: "memory");
        }

        // ---- MMA mainloop: main = xh*Wh (f32 acc); res = xh*Wl + xl*Wh (f16 acc) ----
        float    d[2][8][4];
        uint32_t dr[2][8][2];
#pragma unroll
        for (int mb = 0; mb < 2; mb++)
#pragma unroll
            for (int nb = 0; nb < 8; nb++) {
#pragma unroll
                for (int j = 0; j < 4; j++) d[mb][nb][j] = 0.0f;
                dr[mb][nb][0] = 0u; dr[mb][nb][1] = 0u;
            }

#pragma unroll
        for (int k = 0; k < 8; k++) {
            const uint32_t ko = (uint32_t)k * 32;
            uint32_t ah[2][4], al[2][4];
            ldsm_x4(aAddr0H + ko,       ah[0][0], ah[0][1], ah[0][2], ah[0][3]);
            ldsm_x4(aAddr0H + dXL + ko, al[0][0], al[0][1], al[0][2], al[0][3]);
            ldsm_x4(aAddr1H + ko,       ah[1][0], ah[1][1], ah[1][2], ah[1][3]);
            ldsm_x4(aAddr1H + dXL + ko, al[1][0], al[1][1], al[1][2], al[1][3]);
#pragma unroll
            for (int nb = 0; nb < 4; nb++) {
                uint32_t bh0, bh1, bh2, bh3, bl0, bl1, bl2, bl3;
                const uint32_t boff = (uint32_t)nb * (16 * ROWB) + ko;
                ldsm_x4(bBaseH + boff,       bh0, bh1, bh2, bh3);
                ldsm_x4(bBaseH + dWL + boff, bl0, bl1, bl2, bl3);
#pragma unroll
                for (int mb = 0; mb < 2; mb++) {
                    mma_f32acc(d[mb][nb * 2],      ah[mb][0], ah[mb][1], ah[mb][2], ah[mb][3], bh0, bh1);
                    mma_f16acc(dr[mb][nb * 2],     ah[mb][0], ah[mb][1], ah[mb][2], ah[mb][3], bl0, bl1);
                    mma_f16acc(dr[mb][nb * 2],     al[mb][0], al[mb][1], al[mb][2], al[mb][3], bh0, bh1);
                    mma_f32acc(d[mb][nb * 2 + 1],  ah[mb][0], ah[mb][1], ah[mb][2], ah[mb][3], bh2, bh3);
                    mma_f16acc(dr[mb][nb * 2 + 1], ah[mb][0], ah[mb][1], ah[mb][2], ah[mb][3], bl2, bl3);
                    mma_f16acc(dr[mb][nb * 2 + 1], al[mb][0], al[mb][1], al[mb][2], al[mb][3], bh2, bh3);
                }
            }
        }

        // ---- epilogue: z = main + residual; partial of ctx . tanh(z + b) ----
#pragma unroll
        for (int mb = 0; mb < 2; mb++) {
            float p0 = 0.0f, p1 = 0.0f;
#pragma unroll
            for (int nb = 0; nb < 8; nb++) {
                const int n0 = colG + nb * 8 + (lane & 3) * 2;
                const float2 bb = *reinterpret_cast<const float2*>(&bS[n0]);
                const float2 cc = *reinterpret_cast<const float2*>(&cS[n0]);
                const float2 r0 = __half22float2(*reinterpret_cast<const __half2*>(&dr[mb][nb][0]));
                const float2 r1 = __half22float2(*reinterpret_cast<const __half2*>(&dr[mb][nb][1]));
                p0 = fmaf(fast_tanh(d[mb][nb][0] + r0.x + bb.x), cc.x, p0);
                p0 = fmaf(fast_tanh(d[mb][nb][1] + r0.y + bb.y), cc.y, p0);
                p1 = fmaf(fast_tanh(d[mb][nb][2] + r1.x + bb.x), cc.x, p1);
                p1 = fmaf(fast_tanh(d[mb][nb][3] + r1.y + bb.y), cc.y, p1);
            }
            p0 += __shfl_xor_sync(0xffffffffu, p0, 1);
            p0 += __shfl_xor_sync(0xffffffffu, p0, 2);
            p1 += __shfl_xor_sync(0xffffffffu, p1, 1);
            p1 += __shfl_xor_sync(0xffffffffu, p1, 2);
            if ((lane & 3) == 0) {
                const int r = rowG + mb * 16 + (lane >> 2);
                pS[r * 2 + (wid & 1)]       = p0;
                pS[(r + 8) * 2 + (wid & 1)] = p1;
            }
        }
        bar64(barid);   // group's partials visible; group's ldsm of this tile done

        // ---- finalize own rows (even thread of each pair) ----
        if ((tid & 1) == 0) {
            const int tok = tbase + xr;
            const float s = (pS[xr * 2] + pS[xr * 2 + 1]) * 0.08838834764831845f;
            const int m = mask[tok];
            const float e = (m == 0) ? 0.0f : __expf(s);
            g_e[tok] = e;
            if (m != 0) {
                const int seg = (tok / Nq) * IDXq + index[tok];
                atomicAdd(&g_segsum[seg], e);
                atomicAdd(&g_cnt[seg], 1);
            }
        }

        // ---- convert raw -> hi/lo (+ fp16 copy) for next tile ----
        asm volatile("cp.async.wait_group 0;" ::: "memory");
        if (next < TILES) {
            const int tokN = next * TM + xr;
            const int mN = mask[tokN];
            __half* xqrow = g_xq + (size_t)tokN * Eq + half;
#pragma unroll
            for (int i = 0; i < 8; i++) {
                float4 f0 = *reinterpret_cast<const float4*>(smem + (rawBase - sb) + i * 32);
                float4 f1 = *reinterpret_cast<const float4*>(smem + (rawBase - sb) + i * 32 + 16);
                float fv[8] = {f0.x, f0.y, f0.z, f0.w, f1.x, f1.y, f1.z, f1.w};
                float hv[8], lv[8];
#pragma unroll
                for (int j = 0; j < 8; j++) {
                    hv[j] = __half2float(__float2half_rn(fv[j]));
                    lv[j] = fv[j] - hv[j];
                }
                uint4 uh, ul;
                uh.x = pack_f16x2(hv[0], hv[1]); uh.y = pack_f16x2(hv[2], hv[3]);
                uh.z = pack_f16x2(hv[4], hv[5]); uh.w = pack_f16x2(hv[6], hv[7]);
                ul.x = pack_f16x2(lv[0], lv[1]); ul.y = pack_f16x2(lv[2], lv[3]);
                ul.z = pack_f16x2(lv[4], lv[5]); ul.w = pack_f16x2(lv[6], lv[7]);
                const int c = half + i * 8;
                *reinterpret_cast<uint4*>(smem + SM_XH + xr * ROWB + c * 2) = uh;
                *reinterpret_cast<uint4*>(smem + SM_XL + xr * ROWB + c * 2) = ul;
                if (mN) *reinterpret_cast<uint4*>(xqrow + i * 8) = uh;
            }
        }
        bar64(barid);   // group's new XH/XL ready before next MMA
        tile = next;
    }
}

// ---------------------------------------------------------------------------
// Scan: exclusive prefix sum of g_cnt -> g_off/g_cur. Shfl-based, 1 block.
// ---------------------------------------------------------------------------
__global__ void __launch_bounds__(1024) scan_kernel() {
    __shared__ int wsum[32];
    const int tid  = threadIdx.x;
    const int lane = tid & 31;
    const int warp = tid >> 5;

    int4 c0 = reinterpret_cast<const int4*>(g_cnt)[tid * 2];
    int4 c1 = reinterpret_cast<const int4*>(g_cnt)[tid * 2 + 1];
    int v[8] = {c0.x, c0.y, c0.z, c0.w, c1.x, c1.y, c1.z, c1.w};
    int pre[8];
    int s = 0;
#pragma unroll
    for (int j = 0; j < 8; j++) { pre[j] = s; s += v[j]; }

    int inc = s;
#pragma unroll
    for (int o = 1; o < 32; o <<= 1) {
        int t = __shfl_up_sync(0xffffffffu, inc, o);
        if (lane >= o) inc += t;
    }
    if (lane == 31) wsum[warp] = inc;
    __syncthreads();
    if (warp == 0) {
        int w = wsum[lane];
#pragma unroll
        for (int o = 1; o < 32; o <<= 1) {
            int t = __shfl_up_sync(0xffffffffu, w, o);
            if (lane >= o) w += t;
        }
        wsum[lane] = w;
    }
    __syncthreads();
    const int base = (warp > 0 ? wsum[warp - 1] : 0) + inc - s;
#pragma unroll
    for (int j = 0; j < 8; j++) {
        const int o = base + pre[j];
        g_off[tid * 8 + j] = o;
        g_cur[tid * 8 + j] = o;
    }
}

// ---------------------------------------------------------------------------
// Place: counting-sort UNMASKED tokens; precompute normalized weights;
// write attn for ALL tokens (0 when masked).
// ---------------------------------------------------------------------------
__global__ void place_kernel(const int* __restrict__ index, const int* __restrict__ mask,
                             float* __restrict__ attn) {
    const int t = blockIdx.x * blockDim.x + threadIdx.x;  // grid exact: TOT
    const int m = mask[t];
    float w = 0.0f;
    if (m != 0) {
        const int seg = (t / Nq) * IDXq + index[t];
        w = g_e[t] / g_segsum[seg];     // segsum > 0: this token contributes
        const int pos = atomicAdd(&g_cur[seg], 1);
        g_ord[pos] = t;
        g_w[pos] = w;
    }
    attn[t] = w;
}

// ---------------------------------------------------------------------------
// Gather: one warp per segment, fp16 rows, streaming ord/w.
// ---------------------------------------------------------------------------
__global__ void __launch_bounds__(256) gather_kernel(float* __restrict__ out)
{
    const int seg  = (blockIdx.x * blockDim.x + threadIdx.x) >> 5; // grid exact: SEGS warps
    const int lane = threadIdx.x & 31;
    const int start = g_off[seg];
    const int end   = g_cur[seg];

    float4 acc = make_float4(0.f, 0.f, 0.f, 0.f);
    int i = start;
    for (; i + 8 <= end; i += 8) {
        int tt[8]; float ww[8]; uint2 vv[8];
#pragma unroll
        for (int j = 0; j < 8; j++) { tt[j] = g_ord[i + j]; ww[j] = g_w[i + j]; }
#pragma unroll
        for (int j = 0; j < 8; j++)
            vv[j] = *reinterpret_cast<const uint2*>(g_xq + (size_t)tt[j] * Eq + lane * 4);
#pragma unroll
        for (int j = 0; j < 8; j++) {
            const float2 f0 = __half22float2(*reinterpret_cast<__half2*>(&vv[j].x));
            const float2 f1 = __half22float2(*reinterpret_cast<__half2*>(&vv[j].y));
            acc.x = fmaf(ww[j], f0.x, acc.x);
            acc.y = fmaf(ww[j], f0.y, acc.y);
            acc.z = fmaf(ww[j], f1.x, acc.z);
            acc.w = fmaf(ww[j], f1.y, acc.w);
        }
    }
    for (; i < end; i++) {
        const int t = g_ord[i];
        const float w = g_w[i];
        uint2 v = *reinterpret_cast<const uint2*>(g_xq + (size_t)t * Eq + lane * 4);
        const float2 f0 = __half22float2(*reinterpret_cast<__half2*>(&v.x));
        const float2 f1 = __half22float2(*reinterpret_cast<__half2*>(&v.y));
        acc.x = fmaf(w, f0.x, acc.x);
        acc.y = fmaf(w, f0.y, acc.y);
        acc.z = fmaf(w, f1.x, acc.z);
        acc.w = fmaf(w, f1.y, acc.w);
    }
    reinterpret_cast<float4*>(out + (size_t)seg * Eq)[lane] = acc;
}

// ---------------------------------------------------------------------------
extern "C" void kernel_launch(void* const* d_in, const int* in_sizes, int n_in,
                              void* d_out, int out_size)
{
    const float* x     = (const float*)d_in[0];
    const float* W     = (const float*)d_in[1];
    const float* bias  = (const float*)d_in[2];
    const float* ctx   = (const float*)d_in[3];
    const int*   mask  = (const int*)d_in[4];
    const int*   index = (const int*)d_in[5];

    float* out  = (float*)d_out;        // [B, IDX, E]
    float* attn = out + OUTF;           // [B, N]

    cudaFuncSetAttribute(score_kernel, cudaFuncAttributeMaxDynamicSharedMemorySize, SM_TOTAL);

    wprep_kernel<<<Eq * Eq / 256, 256>>>(W);
    zinit_kernel<<<SEGS / 256, 256>>>();
    score_kernel<<<152, 256, SM_TOTAL>>>(x, bias, ctx, mask, index);
    scan_kernel<<<1, 1024>>>();
    place_kernel<<<TOT / 256, 256>>>(index, mask, attn);
    gather_kernel<<<SEGS / 8, 256>>>(out);
}